// round 17
// baseline (speedup 1.0000x reference)
#include <cuda_runtime.h>
#include <cuda_bf16.h>
#include <cstdint>

// R17: Stage A reads fp32 features DIRECTLY (no feat-prep pass):
// cp.async fp32 tile -> in-register convert -> bf16 A tile, restructured to
// TILE_M=64 / 256 threads / 112KB smem so 2 CTAs co-reside per SM (the
// co-resident CTA hides convert+sync latency). Edge kernel + fused finalize
// unchanged from R16.

namespace {
constexpr int NHID     = 128;
constexpr int PRE_N    = 256;                 // u(128) | v(128)
constexpr int PRE_K    = 128;
constexpr int TILE_M   = 64;
constexpr int PRE_THREADS = 256;
constexpr int N_NODES_PAD = 100096;
constexpr int PRE_B_BYTES = PRE_K * PRE_N * 2;    // 64 KB W1 image
constexpr int F_BYTES = TILE_M * PRE_K * 4;       // 32 KB fp32 staging
constexpr int A_BYTES = TILE_M * PRE_K * 2;       // 16 KB bf16 A tile
constexpr int OFF_F = PRE_B_BYTES;
constexpr int OFF_A = PRE_B_BYTES + F_BYTES;
constexpr int PRE_DSMEM = OFF_A + A_BYTES + 1024; // ~113 KB < 113.5 (2 CTAs)
constexpr int EDGE_THREADS = 256;
constexpr int W1_ELEMS = PRE_K * PRE_N;           // 32768
}

__device__ __align__(16) __nv_bfloat16 g_w1pre[W1_ELEMS];   // swizzled B image
__device__ __align__(16) __nv_bfloat16 g_uv[(size_t)N_NODES_PAD * PRE_N];
__device__ double g_loss_sum;
__device__ unsigned int g_cnt;

__device__ __forceinline__ uint32_t smem_u32(const void* p) {
    uint32_t a;
    asm("{ .reg .u64 t; cvta.to.shared.u64 t, %1; cvt.u32.u64 %0, t; }" : "=r"(a) : "l"(p));
    return a;
}

#define LDSM_X4(r, addr) \
    asm volatile("ldmatrix.sync.aligned.m8n8.x4.shared.b16 {%0,%1,%2,%3}, [%4];" \
        : "=r"((r)[0]), "=r"((r)[1]), "=r"((r)[2]), "=r"((r)[3]) : "r"(addr))
#define LDSM_X4T(r, addr) \
    asm volatile("ldmatrix.sync.aligned.m8n8.x4.trans.shared.b16 {%0,%1,%2,%3}, [%4];" \
        : "=r"((r)[0]), "=r"((r)[1]), "=r"((r)[2]), "=r"((r)[3]) : "r"(addr))

// ---------------- prep: loss init + W1 image only ----------------
__global__ void hx_prep(const float* __restrict__ W1)
{
    const int idx = blockIdx.x * blockDim.x + threadIdx.x;
    if (idx == 0) { g_loss_sum = 0.0; g_cnt = 0u; }
    if (idx < W1_ELEMS) {
        const int k = idx >> 8, np = idx & 255;
        const int srow = k + ((np >> 7) << 7);
        const int scol = np & 127;
        const int c  = np >> 3;
        const int cs = (c & 24) | ((c & 7) ^ (k & 7));
        const uint32_t off = (uint32_t)k * 512u + (uint32_t)cs * 16u + (uint32_t)(np & 7) * 2u;
        *reinterpret_cast<__nv_bfloat16*>(reinterpret_cast<char*>(g_w1pre) + off) =
            __float2bfloat16(W1[srow * 128 + scol]);
    }
}

// ---------------- Stage A: node GEMM uv = feat @ [W1_top | W1_bot] ----------------
// cp.async the fp32 tile: 64 rows x 512B, thread r=tid>>2, part=tid&3 (128B each)
__device__ __forceinline__ void gather_f32(uint32_t Fbuf, int t, int tid,
                                           const float* __restrict__ feat, int nmax)
{
    const int r = tid >> 2, part = tid & 3;
    int node = t * TILE_M + r;
    if (node > nmax) node = nmax;
    const char* src = reinterpret_cast<const char*>(feat + (size_t)node * PRE_K)
                    + part * 128;
    const uint32_t dst = Fbuf + (uint32_t)r * 512u + (uint32_t)part * 128u;
    #pragma unroll
    for (int q = 0; q < 8; ++q)
        asm volatile("cp.async.cg.shared.global [%0], [%1], 16;"
                     :: "r"(dst + (uint32_t)q * 16u), "l"(src + q * 16) : "memory");
}

__global__ __launch_bounds__(PRE_THREADS, 2)
void hx_pre_gemm(const float* __restrict__ feature,
                 const float* __restrict__ b1, int ntiles, int nmax)
{
    extern __shared__ char dyn[];
    const int tid  = threadIdx.x;
    const int lane = tid & 31;
    const int warp = tid >> 5;          // 0..7 = warp_n

    const uint32_t dynb = smem_u32(dyn);
    const uint32_t base = (dynb + 1023u) & ~1023u;
    char* dynbase = dyn + (base - dynb);
    const uint32_t Bsm  = base;
    const uint32_t Fbuf = base + OFF_F;
    const uint32_t Abuf = base + OFF_A;

    const int warp_n = warp;
    const int n_base = warp_n * 32;
    const int quad = lane >> 2, qlane = lane & 3;

    // prologue: first fp32 tile + B image
    if (blockIdx.x < ntiles) gather_f32(Fbuf, blockIdx.x, tid, feature, nmax);
    asm volatile("cp.async.commit_group;" ::: "memory");
    {
        const int4* s = reinterpret_cast<const int4*>(g_w1pre);
        int4* d = reinterpret_cast<int4*>(dynbase);
        for (int i = tid; i < PRE_B_BYTES / 16; i += PRE_THREADS) d[i] = s[i];
    }

    float2 bb[4];
    #pragma unroll
    for (int j = 0; j < 4; ++j) {
        const int n = n_base + j * 8 + qlane * 2;
        bb[j] = (n < 128) ? make_float2(b1[n], b1[n + 1]) : make_float2(0.f, 0.f);
    }

    uint32_t rowA[4];
    #pragma unroll
    for (int i = 0; i < 4; ++i)
        rowA[i] = Abuf + (uint32_t)(i * 16 + (lane & 15)) * 256u;
    const int xA  = lane & 7;
    const int csA = lane >> 4;

    uint32_t bBase[2];
    {
        const int kr = lane & 15;
        #pragma unroll
        for (int j2 = 0; j2 < 2; ++j2) {
            const int cn = warp_n * 4 + j2 * 2 + (lane >> 4);
            const int cs = (cn & 24) | ((cn & 7) ^ (kr & 7));
            bBase[j2] = Bsm + (uint32_t)kr * 512u + (uint32_t)cs * 16u;
        }
    }

    // convert identity: r = tid>>2 (4 threads/row), chunks part*4..+3 (16B bf16 each)
    const int cv_r = tid >> 2, cv_part = tid & 3;
    const uint32_t cv_fbase = Fbuf + (uint32_t)cv_r * 512u;
    const uint32_t cv_abase = Abuf + (uint32_t)cv_r * 256u;

    for (int t = blockIdx.x; t < ntiles; t += gridDim.x) {
        asm volatile("cp.async.wait_group 0;" ::: "memory");
        __syncthreads();    // F ready; previous GEMM done reading A

        // ---- convert F (fp32) -> A (bf16, swizzled) ----
        #pragma unroll
        for (int q = 0; q < 4; ++q) {
            const int c = cv_part * 4 + q;
            const float4 v0 = *reinterpret_cast<const float4*>(
                dyn + (cv_fbase - dynb) + c * 32);
            const float4 v1 = *reinterpret_cast<const float4*>(
                dyn + (cv_fbase - dynb) + c * 32 + 16);
            const __nv_bfloat162 p0 = __floats2bfloat162_rn(v0.x, v0.y);
            const __nv_bfloat162 p1 = __floats2bfloat162_rn(v0.z, v0.w);
            const __nv_bfloat162 p2 = __floats2bfloat162_rn(v1.x, v1.y);
            const __nv_bfloat162 p3 = __floats2bfloat162_rn(v1.z, v1.w);
            const int cs = (c & 8) | ((c & 7) ^ (cv_r & 7));
            uint4 pk;
            pk.x = *reinterpret_cast<const uint32_t*>(&p0);
            pk.y = *reinterpret_cast<const uint32_t*>(&p1);
            pk.z = *reinterpret_cast<const uint32_t*>(&p2);
            pk.w = *reinterpret_cast<const uint32_t*>(&p3);
            asm volatile("st.shared.v4.b32 [%0], {%1,%2,%3,%4};"
                         :: "r"(cv_abase + (uint32_t)cs * 16u),
                            "r"(pk.x), "r"(pk.y), "r"(pk.z), "r"(pk.w) : "memory");
        }
        __syncthreads();    // A complete; F free for next fetch

        const int tn = t + gridDim.x;
        if (tn < ntiles) {
            gather_f32(Fbuf, tn, tid, feature, nmax);
            asm volatile("cp.async.commit_group;" ::: "memory");
        }

        // ---- GEMM: warp tile m64n32, 8 k-steps ----
        float acc[4][4][4];
        #pragma unroll
        for (int i = 0; i < 4; ++i)
            #pragma unroll
            for (int j = 0; j < 4; ++j) {
                acc[i][j][0] = 0.f; acc[i][j][1] = 0.f;
                acc[i][j][2] = 0.f; acc[i][j][3] = 0.f;
            }

        #pragma unroll
        for (int ks = 0; ks < 8; ++ks) {
            uint32_t b[2][4], a[4][4];
            #pragma unroll
            for (int j2 = 0; j2 < 2; ++j2)
                LDSM_X4T(b[j2], bBase[j2] + (uint32_t)ks * 8192u);
            const int c  = 2 * ks + csA;
            const int cs = (c & 8) | ((c & 7) ^ xA);
            #pragma unroll
            for (int i = 0; i < 4; ++i)
                LDSM_X4(a[i], rowA[i] + (uint32_t)cs * 16u);
            #pragma unroll
            for (int i = 0; i < 4; ++i)
                #pragma unroll
                for (int j = 0; j < 4; ++j) {
                    const uint32_t bb0 = b[j >> 1][(j & 1) * 2];
                    const uint32_t bb1 = b[j >> 1][(j & 1) * 2 + 1];
                    asm volatile(
                        "mma.sync.aligned.m16n8k16.row.col.f32.bf16.bf16.f32 "
                        "{%0,%1,%2,%3}, {%4,%5,%6,%7}, {%8,%9}, {%0,%1,%2,%3};"
                        : "+f"(acc[i][j][0]), "+f"(acc[i][j][1]),
                          "+f"(acc[i][j][2]), "+f"(acc[i][j][3])
                        : "r"(a[i][0]), "r"(a[i][1]), "r"(a[i][2]), "r"(a[i][3]),
                          "r"(bb0), "r"(bb1));
                }
        }

        #pragma unroll
        for (int i = 0; i < 4; ++i) {
            const int m0 = i * 16 + quad;
            const size_t r0 = (size_t)(t * TILE_M + m0) * PRE_N;
            const size_t r1 = (size_t)(t * TILE_M + m0 + 8) * PRE_N;
            #pragma unroll
            for (int j = 0; j < 4; ++j) {
                const int n = n_base + j * 8 + qlane * 2;
                __nv_bfloat162 p = __floats2bfloat162_rn(acc[i][j][0] + bb[j].x,
                                                         acc[i][j][1] + bb[j].y);
                __nv_bfloat162 q = __floats2bfloat162_rn(acc[i][j][2] + bb[j].x,
                                                         acc[i][j][3] + bb[j].y);
                *reinterpret_cast<__nv_bfloat162*>(&g_uv[r0 + n]) = p;
                *reinterpret_cast<__nv_bfloat162*>(&g_uv[r1 + n]) = q;
            }
        }
    }
}

// ---------------- Stage B: per-edge loss + fused finalization ----------------
__global__ __launch_bounds__(EDGE_THREADS, 2)
void hx_edge(const float* __restrict__ alpha,
             const float* __restrict__ W2,
             const float* __restrict__ b2,
             const int* __restrict__ row,
             const int* __restrict__ col,
             const int* __restrict__ label,
             int E, float* __restrict__ out)
{
    __shared__ double s_dsum;
    const int tid  = threadIdx.x;
    const int lane = tid & 31;
    const int warp = tid >> 5;
    if (tid == 0) s_dsum = 0.0;
    __syncthreads();

    const int sub = lane >> 3;
    const int sl  = lane & 7;
    const int ch0 = sl * 16;

    __nv_bfloat162 al2[8];
    float wa[16], wb[16];
    #pragma unroll
    for (int i = 0; i < 8; ++i)
        al2[i] = __floats2bfloat162_rn(__ldg(&alpha[ch0 + 2 * i]),
                                       __ldg(&alpha[ch0 + 2 * i + 1]));
    #pragma unroll
    for (int i = 0; i < 16; ++i) {
        wa[i] = __ldg(&W2[(ch0 + i) * 2]);
        wb[i] = __ldg(&W2[(ch0 + i) * 2 + 1]);
    }
    const float bias0 = b2[0], bias1 = b2[1];
    const __nv_bfloat162 z2 = __floats2bfloat162_rn(0.f, 0.f);

    const int gw = blockIdx.x * (EDGE_THREADS / 32) + warp;
    const int nw = gridDim.x * (EDGE_THREADS / 32);
    const int NG = (E + 3) >> 2;

    double dsum = 0.0;

    if (gw < NG) {
        int e0 = gw * 4 + sub; if (e0 >= E) e0 = E - 1;
        int la = 0, lb = 0;
        uint4 Ua, Ub, Va, Vb;
        {
            const int rc = __ldg(&row[e0]), cc = __ldg(&col[e0]);
            la = __ldg(&label[rc]); lb = __ldg(&label[cc]);
            const __nv_bfloat16* uP = &g_uv[(size_t)rc * PRE_N + ch0];
            const __nv_bfloat16* vP = &g_uv[(size_t)cc * PRE_N + 128 + ch0];
            Ua = *reinterpret_cast<const uint4*>(uP);
            Ub = *reinterpret_cast<const uint4*>(uP + 8);
            Va = *reinterpret_cast<const uint4*>(vP);
            Vb = *reinterpret_cast<const uint4*>(vP + 8);
        }
        int rn = 0, cn = 0;
        if (gw + nw < NG) {
            int e1 = (gw + nw) * 4 + sub; if (e1 >= E) e1 = E - 1;
            rn = __ldg(&row[e1]); cn = __ldg(&col[e1]);
        }

        for (int g = gw; g < NG; g += nw) {
            const int g1 = g + nw;

            uint4 nUa, nUb, nVa, nVb;
            int lan = 0, lbn = 0;
            if (g1 < NG) {
                const __nv_bfloat16* uP = &g_uv[(size_t)rn * PRE_N + ch0];
                const __nv_bfloat16* vP = &g_uv[(size_t)cn * PRE_N + 128 + ch0];
                nUa = *reinterpret_cast<const uint4*>(uP);
                nUb = *reinterpret_cast<const uint4*>(uP + 8);
                nVa = *reinterpret_cast<const uint4*>(vP);
                nVb = *reinterpret_cast<const uint4*>(vP + 8);
                lan = __ldg(&label[rn]);
                lbn = __ldg(&label[cn]);
            } else {
                nUa = make_uint4(0,0,0,0); nUb = nUa; nVa = nUa; nVb = nUa;
            }
            int rn2 = 0, cn2 = 0;
            if (g + 2 * nw < NG) {
                int e2 = (g + 2 * nw) * 4 + sub; if (e2 >= E) e2 = E - 1;
                rn2 = __ldg(&row[e2]); cn2 = __ldg(&col[e2]);
            }

            float p0 = 0.f, p1 = 0.f;
            const uint32_t uw[8] = {Ua.x, Ua.y, Ua.z, Ua.w, Ub.x, Ub.y, Ub.z, Ub.w};
            const uint32_t vw[8] = {Va.x, Va.y, Va.z, Va.w, Vb.x, Vb.y, Vb.z, Vb.w};
            #pragma unroll
            for (int i = 0; i < 8; ++i) {
                const __nv_bfloat162 u2 = *reinterpret_cast<const __nv_bfloat162*>(&uw[i]);
                const __nv_bfloat162 v2 = *reinterpret_cast<const __nv_bfloat162*>(&vw[i]);
                const __nv_bfloat162 h2 = __hadd2(u2, v2);
                const __nv_bfloat162 ph2 =
                    __hfma2(al2[i], __hmin2(h2, z2), __hmax2(h2, z2));
                const float2 f = __bfloat1622float2(ph2);
                p0 = fmaf(f.x, wa[2 * i], p0);      p1 = fmaf(f.x, wb[2 * i], p1);
                p0 = fmaf(f.y, wa[2 * i + 1], p0);  p1 = fmaf(f.y, wb[2 * i + 1], p1);
            }
            #pragma unroll
            for (int off = 4; off > 0; off >>= 1) {
                p0 += __shfl_xor_sync(0xffffffffu, p0, off);
                p1 += __shfl_xor_sync(0xffffffffu, p1, off);
            }
            if (sl == 0) {
                const int ecur = g * 4 + sub;
                if (ecur < E) {
                    const float l0 = p0 + bias0;
                    const float l1 = p1 + bias1;
                    const float mx  = fmaxf(l0, l1);
                    const float lse = mx + log1pf(expf(-fabsf(l0 - l1)));
                    dsum += (double)(((la == lb) ? l1 : l0) - lse);
                }
            }

            Ua = nUa; Ub = nUb; Va = nVa; Vb = nVb;
            la = lan; lb = lbn;
            rn = rn2; cn = cn2;
        }
    }

    if (sl == 0) atomicAdd(&s_dsum, dsum);
    __syncthreads();
    if (tid == 0) {
        atomicAdd(&g_loss_sum, s_dsum);
        __threadfence();
        const unsigned int n = atomicAdd(&g_cnt, 1u);
        if (n == gridDim.x - 1) {
            const double total = atomicAdd(&g_loss_sum, 0.0);
            out[0] = (float)(-total / (double)E);
        }
    }
}

extern "C" void kernel_launch(void* const* d_in, const int* in_sizes, int n_in,
                              void* d_out, int out_size) {
    const float* feature = (const float*)d_in[0];
    const float* W1      = (const float*)d_in[1];
    const float* b1      = (const float*)d_in[2];
    const float* alpha   = (const float*)d_in[3];
    const float* W2      = (const float*)d_in[4];
    const float* b2      = (const float*)d_in[5];
    const int*   row     = (const int*)d_in[6];
    const int*   col     = (const int*)d_in[7];
    const int*   label   = (const int*)d_in[8];
    const int E  = in_sizes[6];
    const int nf = in_sizes[0];
    float* out = (float*)d_out;

    int sms = 148;
    cudaDeviceGetAttribute(&sms, cudaDevAttrMultiProcessorCount, 0);
    cudaFuncSetAttribute(hx_pre_gemm,
                         cudaFuncAttributeMaxDynamicSharedMemorySize, PRE_DSMEM);

    hx_prep<<<(W1_ELEMS + 255) / 256, 256>>>(W1);

    const int nnodes = nf / NHID;
    const int ntiles = (nnodes + TILE_M - 1) / TILE_M;
    hx_pre_gemm<<<sms * 2, PRE_THREADS, PRE_DSMEM>>>(feature, b1, ntiles, nnodes - 1);

    hx_edge<<<sms * 2, EDGE_THREADS>>>(alpha, W2, b2, row, col, label, E, out);
}